// round 14
// baseline (speedup 1.0000x reference)
#include <cuda_runtime.h>
#include <cuda_bf16.h>
#include <stdint.h>

typedef unsigned long long ull;

#define NB   1024
#define SS   16
#define AA   8
#define NACT 16
#define SD   256
#define EM   256
#define NROWS (NB*SS*AA)   // 131072

// ---------------- device scratch ----------------
__device__ float g_sW1[NB*EM];
__device__ float g_v[NB];
__device__ unsigned char g_pos[NROWS];
// h1 A-fragments: [b][mblk(8)][kblk(16)][lane(32)][reg(4)] u32, hi and lo
__device__ uint32_t g_Ah[(size_t)NB*8*16*32*4];
__device__ uint32_t g_Al[(size_t)NB*8*16*32*4];
// W2 B-fragments: [kblk(16)][nblk(32)][lane(32)][reg(2)] u32 (split hi/lo)
__device__ uint32_t g_Bh[16*32*32*2];
__device__ uint32_t g_Bl[16*32*32*2];

// ---------------- threefry2x32 (JAX exact, key(42)) ----------------
__device__ __forceinline__ uint32_t rotl(uint32_t x, int r){ return (x<<r)|(x>>(32-r)); }
__device__ __forceinline__ void threefry2x32(uint32_t c0, uint32_t c1, uint32_t &o0, uint32_t &o1){
  const uint32_t k0 = 0u, k1v = 42u, k2 = 0u ^ 42u ^ 0x1BD11BDAu;
  uint32_t x0 = c0 + k0;
  uint32_t x1 = c1 + k1v;
#define TF_R(rot) { x0 += x1; x1 = rotl(x1, rot); x1 ^= x0; }
  TF_R(13) TF_R(15) TF_R(26) TF_R(6)
  x0 += k1v; x1 += k2 + 1u;
  TF_R(17) TF_R(29) TF_R(16) TF_R(24)
  x0 += k2;  x1 += k0 + 2u;
  TF_R(13) TF_R(15) TF_R(26) TF_R(6)
  x0 += k0;  x1 += k1v + 3u;
  TF_R(17) TF_R(29) TF_R(16) TF_R(24)
  x0 += k1v; x1 += k2 + 4u;
  TF_R(13) TF_R(15) TF_R(26) TF_R(6)
  x0 += k2;  x1 += k0 + 5u;
#undef TF_R
  o0 = x0; o1 = x1;
}
__device__ __forceinline__ float bits_to_unit(uint32_t bits){
  return __uint_as_float(0x3f800000u | (bits >> 9)) - 1.0f;
}

// ---------------- packed helpers ----------------
__device__ __forceinline__ ull pack2(float x){
  ull r; unsigned u = __float_as_uint(x);
  asm("mov.b64 %0, {%1,%1};" : "=l"(r) : "r"(u));
  return r;
}
__device__ __forceinline__ void fma2(ull& d, ull a, ull b){
  asm("fma.rn.f32x2 %0, %1, %2, %0;" : "+l"(d) : "l"(a), "l"(b));
}
__device__ __forceinline__ float2 unpack2(ull v){
  unsigned lo, hi; asm("mov.b64 {%0,%1}, %2;" : "=r"(lo), "=r"(hi) : "l"(v));
  return make_float2(__uint_as_float(lo), __uint_as_float(hi));
}
__device__ __forceinline__ uint32_t pack_bf16x2(float v0, float v1){
  uint32_t r;
  asm("cvt.rn.bf16x2.f32 %0, %1, %2;" : "=r"(r) : "f"(v1), "f"(v0));
  return r;
}
__device__ __forceinline__ void split2(float v0, float v1, uint32_t &h, uint32_t &l){
  h = pack_bf16x2(v0, v1);
  float h0 = __uint_as_float(h << 16);
  float h1 = __uint_as_float(h & 0xFFFF0000u);
  l = pack_bf16x2(v0 - h0, v1 - h1);
}
__device__ __forceinline__ void split_bf16(float v, uint32_t &h, uint32_t &l){
  __nv_bfloat16 hb = __float2bfloat16(v);
  float lf = v - __bfloat162float(hb);
  __nv_bfloat16 lb = __float2bfloat16(lf);
  h = (uint32_t)__bfloat16_as_ushort(hb);
  l = (uint32_t)__bfloat16_as_ushort(lb);
}

__device__ __forceinline__ void mma16816(float* d, const uint32_t* a, uint32_t b0, uint32_t b1){
  asm volatile("mma.sync.aligned.m16n8k16.row.col.f32.bf16.bf16.f32 "
    "{%0,%1,%2,%3}, {%4,%5,%6,%7}, {%8,%9}, {%0,%1,%2,%3};"
    : "+f"(d[0]),"+f"(d[1]),"+f"(d[2]),"+f"(d[3])
    : "r"(a[0]),"r"(a[1]),"r"(a[2]),"r"(a[3]), "r"(b0),"r"(b1));
}

// ============ K0: W2 -> B fragments ============
__global__ void k0_prepW2(const float* __restrict__ W2){
  int idx = blockIdx.x*256 + threadIdx.x;   // 32768
  int kp = idx >> 8, n = idx & 255;
  int k = kp*2;
  float v0 = W2[k*EM + n];
  float v1 = W2[(k+1)*EM + n];
  uint32_t h0,l0,h1,l1;
  split_bf16(v0,h0,l0); split_bf16(v1,h1,l1);
  uint32_t hi = h0 | (h1<<16);
  uint32_t lo = l0 | (l1<<16);
  int kblk = kp>>3;
  int reg  = (kp>>2)&1;
  int lane = (n&7)*4 + (kp&3);
  int nblk = n>>3;
  int bidx = ((kblk*32+nblk)*32+lane)*2 + reg;
  g_Bh[bidx] = hi;
  g_Bl[bidx] = lo;
}

// ============ K1: per-b state terms, 4 b per CTA ============
__global__ void __launch_bounds__(256) k1_state(const float* __restrict__ st,
                         const float* __restrict__ W1,
                         const float* __restrict__ b1, const float* __restrict__ Vw1,
                         const float* __restrict__ Vb1, const float* __restrict__ Vw2,
                         const float* __restrict__ Vb2){
  const int b0 = blockIdx.x * 4;
  const int n  = threadIdx.x;
  __shared__ float s_st[4][SD];
  __shared__ float red[4][EM];
  #pragma unroll
  for(int bi=0;bi<4;bi++) s_st[bi][n] = st[(b0+bi)*SD + n];
  __syncthreads();
  float acc[4], accv[4];
  float bb1 = b1[n], vbb = Vb1[n];
  #pragma unroll
  for(int bi=0;bi<4;bi++){ acc[bi]=bb1; accv[bi]=vbb; }
  #pragma unroll 4
  for(int k=0;k<SD;k++){
    float w  = W1 [k*EM + n];
    float vw = Vw1[k*EM + n];
    #pragma unroll
    for(int bi=0;bi<4;bi++){
      float sv = s_st[bi][k];
      acc[bi]  = fmaf(sv, w,  acc[bi]);
      accv[bi] = fmaf(sv, vw, accv[bi]);
    }
  }
  float vw2 = Vw2[n];
  #pragma unroll
  for(int bi=0;bi<4;bi++){
    g_sW1[(b0+bi)*EM + n] = acc[bi];
    red[bi][n] = fmaxf(accv[bi], 0.f) * vw2;
  }
  __syncthreads();
  int w = n >> 5, l = n & 31;
  if (w < 4){
    float s = 0.f;
    #pragma unroll
    for(int t=0;t<8;t++) s += red[w][l + t*32];
    #pragma unroll
    for(int off=16; off>0; off>>=1) s += __shfl_xor_sync(0xFFFFFFFFu, s, off);
    if (l == 0) g_v[b0 + w] = s + Vb2[0];
  }
}

// ============ K2: RNG + perms + prefix layer-1 -> A fragments (f32x2 + packed cvt) ============
__global__ void __launch_bounds__(256) k2_layer1(const float* __restrict__ qs,
                                                 const float* __restrict__ W1){
  const int b = blockIdx.x;
  const int tid = threadIdx.x;
  __shared__ int   s_inv[SS][AA];
  __shared__ float s_rqT[2048];  // [(sgrp*8+j)*16+na][sl(4)]

  if(tid < SS){
    int s = tid;
    unsigned base = (unsigned)((b*SS + s)*AA);
    float u[AA];
    #pragma unroll
    for(int a=0;a<AA;a++){
      unsigned g = base + a;
      uint32_t o0, o1;
      threefry2x32(0u, g, o0, o1);
      u[a] = bits_to_unit(o0 ^ o1);
    }
    int ord[AA];
    #pragma unroll
    for(int i=0;i<AA;i++) ord[i]=i;
    for(int i=1;i<AA;i++){
      int oi = ord[i]; float ku = u[oi]; int j=i;
      while(j>0 && u[ord[j-1]] > ku){ ord[j]=ord[j-1]; j--; }
      ord[j]=oi;
    }
    #pragma unroll
    for(int r=0;r<AA;r++) s_inv[s][ord[r]] = r;
    #pragma unroll
    for(int i=0;i<AA;i++) g_pos[base + i] = (unsigned char)ord[i];
  }
  __syncthreads();
  for(int e=tid; e<2048; e+=256){
    int sl = e & 3;
    int na = (e >> 2) & 15;
    int j  = (e >> 6) & 7;
    int sg = e >> 9;
    int s  = sg*4 + sl;
    s_rqT[e] = qs[b*(AA*NACT) + s_inv[s][j]*NACT + na];
  }
  __syncthreads();

  const int sgrp = tid >> 6;
  const int cg   = tid & 63;
  const int kblk = cg >> 2;
  const int kp   = cg & 3;
  const int c0   = kblk*16 + kp*2;

  ull acc[4][2];
  {
    ull a01 = *(const ull*)&g_sW1[b*EM + c0];
    ull a89 = *(const ull*)&g_sW1[b*EM + c0 + 8];
    #pragma unroll
    for(int sl=0;sl<4;sl++){ acc[sl][0]=a01; acc[sl][1]=a89; }
  }

  for(int j=0;j<AA;j++){
    #pragma unroll
    for(int na=0;na<NACT;na++){
      const float* wr = &W1[(SD + j*NACT + na)*EM + c0];
      ull w01 = *(const ull*)wr;
      ull w89 = *(const ull*)(wr + 8);
      float4 q4 = *(const float4*)&s_rqT[((sgrp*8 + j)*16 + na)*4];
      ull q;
      q = pack2(q4.x); fma2(acc[0][0],q,w01); fma2(acc[0][1],q,w89);
      q = pack2(q4.y); fma2(acc[1][0],q,w01); fma2(acc[1][1],q,w89);
      q = pack2(q4.z); fma2(acc[2][0],q,w01); fma2(acc[2][1],q,w89);
      q = pack2(q4.w); fma2(acc[3][0],q,w01); fma2(acc[3][1],q,w89);
    }
    const int lane = j*4 + kp;
    #pragma unroll
    for(int p=0;p<2;p++){
      int mblk = sgrp*2 + p;
      float2 x0 = unpack2(acc[2*p][0]);
      float2 x8 = unpack2(acc[2*p][1]);
      float2 y0 = unpack2(acc[2*p+1][0]);
      float2 y8 = unpack2(acc[2*p+1][1]);
      uint4 hv, lv;
      split2(fmaxf(x0.x,0.f), fmaxf(x0.y,0.f), hv.x, lv.x);
      split2(fmaxf(y0.x,0.f), fmaxf(y0.y,0.f), hv.y, lv.y);
      split2(fmaxf(x8.x,0.f), fmaxf(x8.y,0.f), hv.z, lv.z);
      split2(fmaxf(y8.x,0.f), fmaxf(y8.y,0.f), hv.w, lv.w);
      size_t aidx = ((((size_t)b*8 + mblk)*16 + kblk)*32 + lane)*4;
      *(uint4*)&g_Ah[aidx] = hv;
      *(uint4*)&g_Al[aidx] = lv;
    }
  }
}

// ============ K3: HMMA GEMM2 + fused shapley output ============
__global__ void __launch_bounds__(512,1) k3_mma(const float* __restrict__ b2,
                  const float* __restrict__ W3, const float* __restrict__ b3,
                  float* __restrict__ out){
  __shared__ uint32_t sB[2][2][2048];
  __shared__ float b2s[256], w3s[256];
  __shared__ float sred[128][9];
  __shared__ float advs[128];
  __shared__ unsigned char poss[128];
  const int tid  = threadIdx.x;
  const int lane = tid & 31;
  const int warp = tid >> 5;
  const int mblk = warp & 7;
  const int nh   = warp >> 3;
  const int b    = blockIdx.x;

  if (tid < 256){ b2s[tid] = b2[tid]; w3s[tid] = W3[tid]; }
  if (tid >= 256 && tid < 384) poss[tid-256] = g_pos[b*128 + (tid-256)];
  {
    uint4 h = *(const uint4*)&g_Bh[tid*4];
    uint4 l = *(const uint4*)&g_Bl[tid*4];
    *(uint4*)&sB[0][0][tid*4] = h;
    *(uint4*)&sB[0][1][tid*4] = l;
  }

  float d[16][4];
  #pragma unroll
  for(int i=0;i<16;i++){ d[i][0]=0.f; d[i][1]=0.f; d[i][2]=0.f; d[i][3]=0.f; }

  uint32_t ah[4], al[4];
  {
    size_t a0 = ((((size_t)b*8 + mblk)*16 + 0)*32 + lane)*4;
    *(uint4*)ah = *(const uint4*)&g_Ah[a0];
    *(uint4*)al = *(const uint4*)&g_Al[a0];
  }
  __syncthreads();

  for(int kb=0; kb<16; kb++){
    uint4 nh4, nl4;
    uint32_t ahn[4], aln[4];
    if (kb < 15){
      nh4 = *(const uint4*)&g_Bh[(kb+1)*2048 + tid*4];
      nl4 = *(const uint4*)&g_Bl[(kb+1)*2048 + tid*4];
      size_t an = ((((size_t)b*8 + mblk)*16 + (kb+1))*32 + lane)*4;
      *(uint4*)ahn = *(const uint4*)&g_Ah[an];
      *(uint4*)aln = *(const uint4*)&g_Al[an];
    }
    const uint32_t* curh = sB[kb&1][0];
    const uint32_t* curl = sB[kb&1][1];
    #pragma unroll
    for(int nb=0; nb<16; nb++){
      int ng  = nh*16 + nb;
      int off = (ng*32 + lane)*2;
      uint2 bh = *(const uint2*)&curh[off];
      uint2 bl = *(const uint2*)&curl[off];
      mma16816(d[nb], ah, bh.x, bh.y);
      mma16816(d[nb], al, bh.x, bh.y);
      mma16816(d[nb], ah, bl.x, bl.y);
    }
    if (kb < 15){
      *(uint4*)&sB[(kb+1)&1][0][tid*4] = nh4;
      *(uint4*)&sB[(kb+1)&1][1][tid*4] = nl4;
      #pragma unroll
      for(int i=0;i<4;i++){ ah[i]=ahn[i]; al[i]=aln[i]; }
    }
    __syncthreads();
  }

  // epilogue: relu(d + b2) dot W3
  float p0 = 0.f, p1 = 0.f;
  #pragma unroll
  for(int nb=0; nb<16; nb++){
    int c0 = (nh*16 + nb)*8 + (lane&3)*2;
    float w0 = w3s[c0], w1 = w3s[c0+1];
    float bb0 = b2s[c0], bb1 = b2s[c0+1];
    p0 += fmaxf(d[nb][0]+bb0, 0.f)*w0 + fmaxf(d[nb][1]+bb1, 0.f)*w1;
    p1 += fmaxf(d[nb][2]+bb0, 0.f)*w0 + fmaxf(d[nb][3]+bb1, 0.f)*w1;
  }
  p0 += __shfl_xor_sync(0xFFFFFFFFu, p0, 1);
  p0 += __shfl_xor_sync(0xFFFFFFFFu, p0, 2);
  p1 += __shfl_xor_sync(0xFFFFFFFFu, p1, 1);
  p1 += __shfl_xor_sync(0xFFFFFFFFu, p1, 2);
  if ((lane & 3) == 0){
    int r0 = mblk*16 + (lane>>2);
    sred[r0  ][nh] = p0;
    sred[r0+8][nh] = p1;
  }
  __syncthreads();
  if (tid < 128){
    advs[tid] = b3[0] + sred[tid][0] + sred[tid][1];
  }
  __syncthreads();
  if (tid < 8){
    float sum = 0.f;
    #pragma unroll
    for(int s=0;s<SS;s++){
      sum += advs[s*8 + (int)poss[s*8 + tid]];
    }
    out[b*8 + tid] = g_v[b] + sum * (1.0f/16.0f);
  }
}

extern "C" void kernel_launch(void* const* d_in, const int* in_sizes, int n_in,
                              void* d_out, int out_size){
  const float* states   = (const float*)d_in[0];
  const float* agent_qs = (const float*)d_in[1];
  const float* W1  = (const float*)d_in[2];
  const float* b1  = (const float*)d_in[3];
  const float* W2  = (const float*)d_in[4];
  const float* b2  = (const float*)d_in[5];
  const float* W3  = (const float*)d_in[6];
  const float* b3  = (const float*)d_in[7];
  const float* Vw1 = (const float*)d_in[8];
  const float* Vb1 = (const float*)d_in[9];
  const float* Vw2 = (const float*)d_in[10];
  const float* Vb2 = (const float*)d_in[11];
  float* out = (float*)d_out;

  k0_prepW2<<<128, 256>>>(W2);
  k1_state <<<NB/4, 256>>>(states, W1, b1, Vw1, Vb1, Vw2, Vb2);
  k2_layer1<<<NB, 256>>>(agent_qs, W1);
  k3_mma   <<<NB, 512>>>(b2, W3, b3, out);
}

// round 15
// speedup vs baseline: 1.2052x; 1.2052x over previous
#include <cuda_runtime.h>
#include <cuda_bf16.h>
#include <stdint.h>

typedef unsigned long long ull;

#define NB   1024
#define SS   16
#define AA   8
#define NACT 16
#define SD   256
#define EM   256

// ---------------- device scratch ----------------
__device__ float g_sW1[NB*EM];
__device__ float g_v[NB];
// GEMM2 B (W2^T) fragments: [kblk(16)][nblk(32)][lane(32)][reg(2)] u32, split hi/lo
__device__ uint32_t g_Bh[16*32*32*2];
__device__ uint32_t g_Bl[16*32*32*2];
// GEMM1 B (W1x) fragments: [kblk(8)][nblk(32)][lane(32)][reg(2)] u32, split hi/lo
__device__ uint32_t g_B1h[8*32*32*2];
__device__ uint32_t g_B1l[8*32*32*2];

// ---------------- threefry2x32 (JAX exact, key(42)) ----------------
__device__ __forceinline__ uint32_t rotl(uint32_t x, int r){ return (x<<r)|(x>>(32-r)); }
__device__ __forceinline__ void threefry2x32(uint32_t c0, uint32_t c1, uint32_t &o0, uint32_t &o1){
  const uint32_t k0 = 0u, k1v = 42u, k2 = 0u ^ 42u ^ 0x1BD11BDAu;
  uint32_t x0 = c0 + k0;
  uint32_t x1 = c1 + k1v;
#define TF_R(rot) { x0 += x1; x1 = rotl(x1, rot); x1 ^= x0; }
  TF_R(13) TF_R(15) TF_R(26) TF_R(6)
  x0 += k1v; x1 += k2 + 1u;
  TF_R(17) TF_R(29) TF_R(16) TF_R(24)
  x0 += k2;  x1 += k0 + 2u;
  TF_R(13) TF_R(15) TF_R(26) TF_R(6)
  x0 += k0;  x1 += k1v + 3u;
  TF_R(17) TF_R(29) TF_R(16) TF_R(24)
  x0 += k1v; x1 += k2 + 4u;
  TF_R(13) TF_R(15) TF_R(26) TF_R(6)
  x0 += k2;  x1 += k0 + 5u;
#undef TF_R
  o0 = x0; o1 = x1;
}
__device__ __forceinline__ float bits_to_unit(uint32_t bits){
  return __uint_as_float(0x3f800000u | (bits >> 9)) - 1.0f;
}

// ---------------- packed helpers ----------------
__device__ __forceinline__ uint32_t pack_bf16x2(float v0, float v1){
  uint32_t r;
  asm("cvt.rn.bf16x2.f32 %0, %1, %2;" : "=r"(r) : "f"(v1), "f"(v0));
  return r;
}
__device__ __forceinline__ void split2(float v0, float v1, uint32_t &h, uint32_t &l){
  h = pack_bf16x2(v0, v1);
  float h0 = __uint_as_float(h << 16);
  float h1 = __uint_as_float(h & 0xFFFF0000u);
  l = pack_bf16x2(v0 - h0, v1 - h1);
}
__device__ __forceinline__ void split_bf16(float v, uint32_t &h, uint32_t &l){
  __nv_bfloat16 hb = __float2bfloat16(v);
  float lf = v - __bfloat162float(hb);
  __nv_bfloat16 lb = __float2bfloat16(lf);
  h = (uint32_t)__bfloat16_as_ushort(hb);
  l = (uint32_t)__bfloat16_as_ushort(lb);
}

__device__ __forceinline__ void mma16816(float* d, const uint32_t* a, uint32_t b0, uint32_t b1){
  asm volatile("mma.sync.aligned.m16n8k16.row.col.f32.bf16.bf16.f32 "
    "{%0,%1,%2,%3}, {%4,%5,%6,%7}, {%8,%9}, {%0,%1,%2,%3};"
    : "+f"(d[0]),"+f"(d[1]),"+f"(d[2]),"+f"(d[3])
    : "r"(a[0]),"r"(a[1]),"r"(a[2]),"r"(a[3]), "r"(b0),"r"(b1));
}

// ============ K0: W2 -> GEMM2 B fragments ============
__global__ void k0_prepW2(const float* __restrict__ W2){
  int idx = blockIdx.x*256 + threadIdx.x;   // 32768
  int kp = idx >> 8, n = idx & 255;
  int k = kp*2;
  float v0 = W2[k*EM + n];
  float v1 = W2[(k+1)*EM + n];
  uint32_t h0,l0,h1,l1;
  split_bf16(v0,h0,l0); split_bf16(v1,h1,l1);
  uint32_t hi = h0 | (h1<<16);
  uint32_t lo = l0 | (l1<<16);
  int kblk = kp>>3;
  int reg  = (kp>>2)&1;
  int lane = (n&7)*4 + (kp&3);
  int nblk = n>>3;
  int bidx = ((kblk*32+nblk)*32+lane)*2 + reg;
  g_Bh[bidx] = hi;
  g_Bl[bidx] = lo;
}

// ============ K0b: W1x (rows SD..SD+127) -> GEMM1 B fragments ============
__global__ void k0b_prepW1x(const float* __restrict__ W1){
  int idx = blockIdx.x*256 + threadIdx.x;   // 16384
  int kp = idx >> 8, n = idx & 255;         // kp = 0..63 (k-pair in K=128)
  int k = kp*2;
  float v0 = W1[(SD + k)*EM + n];
  float v1 = W1[(SD + k + 1)*EM + n];
  uint32_t h0,l0,h1,l1;
  split_bf16(v0,h0,l0); split_bf16(v1,h1,l1);
  uint32_t hi = h0 | (h1<<16);
  uint32_t lo = l0 | (l1<<16);
  int kblk = kp>>3;          // 0..7
  int reg  = (kp>>2)&1;
  int lane = (n&7)*4 + (kp&3);
  int nblk = n>>3;
  int bidx = ((kblk*32+nblk)*32+lane)*2 + reg;
  g_B1h[bidx] = hi;
  g_B1l[bidx] = lo;
}

// ============ K1: per-b state terms, 4 b per CTA ============
__global__ void __launch_bounds__(256) k1_state(const float* __restrict__ st,
                         const float* __restrict__ W1,
                         const float* __restrict__ b1, const float* __restrict__ Vw1,
                         const float* __restrict__ Vb1, const float* __restrict__ Vw2,
                         const float* __restrict__ Vb2){
  const int b0 = blockIdx.x * 4;
  const int n  = threadIdx.x;
  __shared__ float s_st[4][SD];
  __shared__ float red[4][EM];
  #pragma unroll
  for(int bi=0;bi<4;bi++) s_st[bi][n] = st[(b0+bi)*SD + n];
  __syncthreads();
  float acc[4], accv[4];
  float bb1 = b1[n], vbb = Vb1[n];
  #pragma unroll
  for(int bi=0;bi<4;bi++){ acc[bi]=bb1; accv[bi]=vbb; }
  #pragma unroll 4
  for(int k=0;k<SD;k++){
    float w  = W1 [k*EM + n];
    float vw = Vw1[k*EM + n];
    #pragma unroll
    for(int bi=0;bi<4;bi++){
      float sv = s_st[bi][k];
      acc[bi]  = fmaf(sv, w,  acc[bi]);
      accv[bi] = fmaf(sv, vw, accv[bi]);
    }
  }
  float vw2 = Vw2[n];
  #pragma unroll
  for(int bi=0;bi<4;bi++){
    g_sW1[(b0+bi)*EM + n] = acc[bi];
    red[bi][n] = fmaxf(accv[bi], 0.f) * vw2;
  }
  __syncthreads();
  int w = n >> 5, l = n & 31;
  if (w < 4){
    float s = 0.f;
    #pragma unroll
    for(int t=0;t<8;t++) s += red[w][l + t*32];
    #pragma unroll
    for(int off=16; off>0; off>>=1) s += __shfl_xor_sync(0xFFFFFFFFu, s, off);
    if (l == 0) g_v[b0 + w] = s + Vb2[0];
  }
}

// ============ Fused: RNG + X-frags + GEMM1(tensor) + GEMM2(tensor) + shapley ============
// smem layout (bytes)
#define S_A2H 0                 // 65536: GEMM2 A hi frags [mblk*16+kblk][lane][4]; first 64KB doubles as X frags during GEMM1
#define S_A2L 65536             // 65536: GEMM2 A lo frags
#define S_XH  0                 // 32768: GEMM1 A (X) hi frags [mblk*8+kblk][lane][4]
#define S_XL  32768             // 32768: GEMM1 A (X) lo frags
#define S_BH  131072            // 16384: B hi dbuf [buf][2048 u32]
#define S_BL  147456            // 16384: B lo dbuf
#define S_RQH 163840            // 4096: rq hi pairs [s(16)][a(8)][pr(8)]
#define S_RQL 167936            // 4096
#define S_SW1 172032            // 1024
#define S_B2  173056            // 1024
#define S_W3  174080            // 1024
#define S_RED 175104            // 4608: sred[128][9]
#define S_ADV 179712            // 512
#define S_POS 180224            // 128
#define S_INV 180352            // 512
#define SM_TOT 180864

__global__ void __launch_bounds__(512,1) kfused(const float* __restrict__ qs,
                  const float* __restrict__ b2, const float* __restrict__ W3,
                  const float* __restrict__ b3, float* __restrict__ out){
  extern __shared__ __align__(16) char sm[];
  uint32_t* sA2h = (uint32_t*)(sm + S_A2H);
  uint32_t* sA2l = (uint32_t*)(sm + S_A2L);
  uint32_t* sXh  = (uint32_t*)(sm + S_XH);
  uint32_t* sXl  = (uint32_t*)(sm + S_XL);
  uint32_t* sBh  = (uint32_t*)(sm + S_BH);
  uint32_t* sBl  = (uint32_t*)(sm + S_BL);
  uint32_t* rqh  = (uint32_t*)(sm + S_RQH);
  uint32_t* rql  = (uint32_t*)(sm + S_RQL);
  float* sW1s = (float*)(sm + S_SW1);
  float* b2s  = (float*)(sm + S_B2);
  float* w3s  = (float*)(sm + S_W3);
  float (*sred)[9] = (float(*)[9])(sm + S_RED);
  float* advs = (float*)(sm + S_ADV);
  unsigned char* poss = (unsigned char*)(sm + S_POS);
  int (*s_inv)[AA] = (int(*)[AA])(sm + S_INV);

  const int tid  = threadIdx.x;
  const int b    = blockIdx.x;
  const int lane = tid & 31;
  const int warp = tid >> 5;
  const int mblk = warp & 7;
  const int nh   = warp >> 3;

  // stage GEMM1 B chunk 0 + constants
  {
    ((uint4*)sBh)[tid & 511] = ((const uint4*)g_B1h)[tid];
    ((uint4*)sBl)[tid & 511] = ((const uint4*)g_B1l)[tid];
  }
  if (tid < 256){
    b2s[tid]  = b2[tid];
    w3s[tid]  = W3[tid];
    sW1s[tid] = g_sW1[b*EM + tid];
  }

  // RNG + permutations
  if (tid < SS){
    int s = tid;
    unsigned base = (unsigned)((b*SS + s)*AA);
    float u[AA];
    #pragma unroll
    for(int a=0;a<AA;a++){
      uint32_t o0, o1;
      threefry2x32(0u, base + a, o0, o1);
      u[a] = bits_to_unit(o0 ^ o1);
    }
    int ord[AA];
    #pragma unroll
    for(int i=0;i<AA;i++) ord[i]=i;
    for(int i=1;i<AA;i++){
      int oi = ord[i]; float ku = u[oi]; int j=i;
      while(j>0 && u[ord[j-1]] > ku){ ord[j]=ord[j-1]; j--; }
      ord[j]=oi;
    }
    #pragma unroll
    for(int r=0;r<AA;r++) s_inv[s][ord[r]] = r;
    #pragma unroll
    for(int i=0;i<AA;i++) poss[s*8 + i] = (unsigned char)ord[i];
  }
  __syncthreads();

  // rq split pairs: rqh/rql[s][a][pr] = bf16x2 of (q[na=2pr], q[na=2pr+1]) of agent inv[s][a]
  for(int e=tid; e<1024; e+=512){
    int s  = e >> 6;
    int a  = (e >> 3) & 7;
    int pr = e & 7;
    const float* qp = &qs[b*(AA*NACT) + s_inv[s][a]*NACT + pr*2];
    float v0 = qp[0], v1 = qp[1];
    uint32_t h, l;
    split2(v0, v1, h, l);
    rqh[e] = h;
    rql[e] = l;
  }
  __syncthreads();

  // X fragment build: [mblk(8)][kblk(8)][lane(32)] uint4
  #pragma unroll
  for(int t=0;t<4;t++){
    int idx = tid + t*512;             // 0..2047
    int mb  = idx >> 8;
    int kb  = (idx >> 5) & 7;          // = agent position a
    int ln  = idx & 31;
    int j   = ln >> 2;
    int pr  = ln & 3;
    uint4 hv = make_uint4(0,0,0,0), lv = make_uint4(0,0,0,0);
    if (kb <= j){
      int s0 = mb*2, s1 = mb*2 + 1;
      int e00 = (s0*8 + kb)*8 + pr;
      int e10 = (s1*8 + kb)*8 + pr;
      hv.x = rqh[e00];   lv.x = rql[e00];
      hv.y = rqh[e10];   lv.y = rql[e10];
      hv.z = rqh[e00+4]; lv.z = rql[e00+4];
      hv.w = rqh[e10+4]; lv.w = rql[e10+4];
    }
    int o = ((mb*8 + kb)*32 + ln)*4;
    *(uint4*)&sXh[o] = hv;
    *(uint4*)&sXl[o] = lv;
  }
  __syncthreads();

  // ---- GEMM1: D1[128,256] = X[128,128] @ W1x ; 16 warps (8 mblk x 2 nh) ----
  float d[16][4];
  #pragma unroll
  for(int i=0;i<16;i++){ d[i][0]=0.f; d[i][1]=0.f; d[i][2]=0.f; d[i][3]=0.f; }

  for(int kb=0; kb<8; kb++){
    uint4 ph, pl;
    if (kb < 7){
      ph = ((const uint4*)(g_B1h + (kb+1)*2048))[tid];
      pl = ((const uint4*)(g_B1l + (kb+1)*2048))[tid];
    }
    uint32_t xh[4], xl[4];
    {
      int o = ((mblk*8 + kb)*32 + lane)*4;
      *(uint4*)xh = *(const uint4*)&sXh[o];
      *(uint4*)xl = *(const uint4*)&sXl[o];
    }
    const uint32_t* curh = &sBh[(kb&1)*2048];
    const uint32_t* curl = &sBl[(kb&1)*2048];
    #pragma unroll
    for(int nb=0; nb<16; nb++){
      int ng  = nh*16 + nb;
      int off = (ng*32 + lane)*2;
      uint2 bh = *(const uint2*)&curh[off];
      uint2 bl = *(const uint2*)&curl[off];
      mma16816(d[nb], xh, bh.x, bh.y);
      mma16816(d[nb], xl, bh.x, bh.y);
      mma16816(d[nb], xh, bl.x, bl.y);
    }
    if (kb < 7){
      ((uint4*)&sBh[((kb+1)&1)*2048])[tid & 511] = ph;
      ((uint4*)&sBl[((kb+1)&1)*2048])[tid & 511] = pl;
    }
    __syncthreads();
  }

  // ---- GEMM1 epilogue: h1 = relu(D1 + sW1) -> split -> A2 frags (thread-local!) ----
  #pragma unroll
  for(int nbp=0; nbp<8; nbp++){
    int nbe = nbp*2, nbo = nbp*2 + 1;
    int ce = nh*128 + nbe*8 + (lane&3)*2;
    int co = nh*128 + nbo*8 + (lane&3)*2;
    float h00 = fmaxf(d[nbe][0] + sW1s[ce],   0.f);
    float h01 = fmaxf(d[nbe][1] + sW1s[ce+1], 0.f);
    float h10 = fmaxf(d[nbe][2] + sW1s[ce],   0.f);
    float h11 = fmaxf(d[nbe][3] + sW1s[ce+1], 0.f);
    float g00 = fmaxf(d[nbo][0] + sW1s[co],   0.f);
    float g01 = fmaxf(d[nbo][1] + sW1s[co+1], 0.f);
    float g10 = fmaxf(d[nbo][2] + sW1s[co],   0.f);
    float g11 = fmaxf(d[nbo][3] + sW1s[co+1], 0.f);
    uint4 hv, lv;
    split2(h00, h01, hv.x, lv.x);
    split2(h10, h11, hv.y, lv.y);
    split2(g00, g01, hv.z, lv.z);
    split2(g10, g11, hv.w, lv.w);
    int kblk2 = nh*8 + nbp;
    int o = ((mblk*16 + kblk2)*32 + lane)*4;
    *(uint4*)&sA2h[o] = hv;
    *(uint4*)&sA2l[o] = lv;
  }
  // stage GEMM2 B chunk 0 (buf 0 free: last GEMM1 chunk was buf 1)
  {
    ((uint4*)sBh)[tid & 511] = ((const uint4*)g_Bh)[tid];
    ((uint4*)sBl)[tid & 511] = ((const uint4*)g_Bl)[tid];
  }
  __syncthreads();

  // ---- GEMM2: adv = relu(h1 @ W2 + b2) . W3 ; R8-proven loop, A from smem ----
  #pragma unroll
  for(int i=0;i<16;i++){ d[i][0]=0.f; d[i][1]=0.f; d[i][2]=0.f; d[i][3]=0.f; }

  for(int kb=0; kb<16; kb++){
    uint4 ph, pl;
    if (kb < 15){
      ph = ((const uint4*)(g_Bh + (kb+1)*2048))[tid];
      pl = ((const uint4*)(g_Bl + (kb+1)*2048))[tid];
    }
    uint32_t ah[4], al[4];
    {
      int o = ((mblk*16 + kb)*32 + lane)*4;
      *(uint4*)ah = *(const uint4*)&sA2h[o];
      *(uint4*)al = *(const uint4*)&sA2l[o];
    }
    const uint32_t* curh = &sBh[(kb&1)*2048];
    const uint32_t* curl = &sBl[(kb&1)*2048];
    #pragma unroll
    for(int nb=0; nb<16; nb++){
      int ng  = nh*16 + nb;
      int off = (ng*32 + lane)*2;
      uint2 bh = *(const uint2*)&curh[off];
      uint2 bl = *(const uint2*)&curl[off];
      mma16816(d[nb], ah, bh.x, bh.y);
      mma16816(d[nb], al, bh.x, bh.y);
      mma16816(d[nb], ah, bl.x, bl.y);
    }
    if (kb < 15){
      ((uint4*)&sBh[((kb+1)&1)*2048])[tid & 511] = ph;
      ((uint4*)&sBl[((kb+1)&1)*2048])[tid & 511] = pl;
    }
    __syncthreads();
  }

  // ---- epilogue: relu(d + b2) dot W3, quad shfl-reduce, shapley ----
  float p0 = 0.f, p1 = 0.f;
  #pragma unroll
  for(int nb=0; nb<16; nb++){
    int c0 = (nh*16 + nb)*8 + (lane&3)*2;
    float w0 = w3s[c0], w1 = w3s[c0+1];
    float bb0 = b2s[c0], bb1 = b2s[c0+1];
    p0 += fmaxf(d[nb][0]+bb0, 0.f)*w0 + fmaxf(d[nb][1]+bb1, 0.f)*w1;
    p1 += fmaxf(d[nb][2]+bb0, 0.f)*w0 + fmaxf(d[nb][3]+bb1, 0.f)*w1;
  }
  p0 += __shfl_xor_sync(0xFFFFFFFFu, p0, 1);
  p0 += __shfl_xor_sync(0xFFFFFFFFu, p0, 2);
  p1 += __shfl_xor_sync(0xFFFFFFFFu, p1, 1);
  p1 += __shfl_xor_sync(0xFFFFFFFFu, p1, 2);
  if ((lane & 3) == 0){
    int r0 = mblk*16 + (lane>>2);
    sred[r0  ][nh] = p0;
    sred[r0+8][nh] = p1;
  }
  __syncthreads();
  if (tid < 128){
    advs[tid] = b3[0] + sred[tid][0] + sred[tid][1];
  }
  __syncthreads();
  if (tid < 8){
    float sum = 0.f;
    #pragma unroll
    for(int s=0;s<SS;s++){
      sum += advs[s*8 + (int)poss[s*8 + tid]];
    }
    out[b*8 + tid] = g_v[b] + sum * (1.0f/16.0f);
  }
}

extern "C" void kernel_launch(void* const* d_in, const int* in_sizes, int n_in,
                              void* d_out, int out_size){
  const float* states   = (const float*)d_in[0];
  const float* agent_qs = (const float*)d_in[1];
  const float* W1  = (const float*)d_in[2];
  const float* b1  = (const float*)d_in[3];
  const float* W2  = (const float*)d_in[4];
  const float* b2  = (const float*)d_in[5];
  const float* W3  = (const float*)d_in[6];
  const float* b3  = (const float*)d_in[7];
  const float* Vw1 = (const float*)d_in[8];
  const float* Vb1 = (const float*)d_in[9];
  const float* Vw2 = (const float*)d_in[10];
  const float* Vb2 = (const float*)d_in[11];
  float* out = (float*)d_out;

  cudaFuncSetAttribute(kfused, cudaFuncAttributeMaxDynamicSharedMemorySize, SM_TOT);

  k0_prepW2  <<<128, 256>>>(W2);
  k0b_prepW1x<<<64, 256>>>(W1);
  k1_state   <<<NB/4, 256>>>(states, W1, b1, Vw1, Vb1, Vw2, Vb2);
  kfused     <<<NB, 512, SM_TOT>>>(agent_qs, b2, W3, b3, out);
}